// round 13
// baseline (speedup 1.0000x reference)
#include <cuda_runtime.h>

// SNN recurrence: B=1024, T=1024, H=32, I=2. One warp/batch, one lane/unit.
// Bit-exact reference-order rounding (rel_err = 0.0 in all prior rounds).
//
// R11: kernel is fma-pipe-throughput-bound (10 rt=2 fma-class ops/warp-step
// = 40 cyc/step-pair at 2 warps/SMSP = measured 41). All five FADDs are now
// compiler-visible __fmaf_rn(x, 0.5f, y) — NO inline asm — so ptxas can use
// the FFMA src1-immediate encoding (rt_SMSP=1, half pipe cost). Companion
// constants pre-doubled (2w0, 2bg, 2bs); spike selects are ternaries
// (FSEL, alu pipe, pred-as-data latency 4). All roundings bit-identical:
//   round(x*2c) = 2*round(x*c)        (exact power-of-2 scaling)
//   fma(t,0.5,y) = round(t/2 + y)     (product exact)
//   fma(-2|0, 0.5, v) = v-1 | v       (only a -0 -> +0 flip, non-propagating)

#define TT 1024

template <bool ACC>
__device__ __forceinline__ void run32(const float2* __restrict__ buf,
                                      float& v, float& V, int& acc,
                                      float W0d, float w1, float ag, float BG2,
                                      float as, float BS2)
{
    // u2 = 2*u, pipelined one step ahead (LDS exposed once per chunk)
    float2 xv = buf[0];
    float u2 = __fmul_rn(BG2,
                 __fmaf_rn(__fmul_rn(xv.x, W0d), 0.5f, __fmul_rn(xv.y, w1)));

    #pragma unroll
    for (int i = 0; i < 32; ++i) {
        // next step's input term (state-independent, off the serial chain)
        float un = 0.0f;
        if (i < 31) {
            float2 xn = buf[i + 1];
            un = __fmul_rn(BG2,
                   __fmaf_rn(__fmul_rn(xn.x, W0d), 0.5f, __fmul_rn(xn.y, w1)));
        }

        // old spikes (as pre-doubled addends)
        const float s2 = (v > 1.0f) ? -2.0f : 0.0f;   // -2*s_{t-1}
        const float S2 = (V > 1.0f) ? -2.0f : 0.0f;   // -2*S_{t-1}

        // v = round(round(ag*v + u) - s)
        v = __fmaf_rn(u2, 0.5f, __fmul_rn(ag, v));
        v = __fmaf_rn(s2, 0.5f, v);

        // new group spike -> soma injection m = bs*s_t
        const float i2 = (v > 1.0f) ? BS2 : 0.0f;     // 2*m

        // V = round(round(as*V + m) - S)
        V = __fmaf_rn(i2, 0.5f, __fmul_rn(as, V));
        V = __fmaf_rn(S2, 0.5f, V);

        if (ACC) acc += (V > 1.0f) ? 1 : 0;           // exact int count (alu)

        u2 = un;
    }
}

__global__ __launch_bounds__(256, 1)
void snn_kernel(const float* __restrict__ x,
                const float* __restrict__ Wg,     // [32,2]
                const float* __restrict__ tau_g,  // [32]
                const float* __restrict__ tau_s,  // [32]
                const float* __restrict__ Wout,   // [32]
                const float* __restrict__ bout,   // [1]
                float* __restrict__ out)          // [1024]
{
    const int lane = threadIdx.x & 31;
    const int wib  = threadIdx.x >> 5;
    const int b    = blockIdx.x * 8 + wib;

    __shared__ float2 sbuf[8][2][32];   // [warp-in-block][double buffer][step]

    const float w0 = Wg[2 * lane];
    const float w1 = Wg[2 * lane + 1];
    const float ag = 1.0f / (1.0f + expf(-tau_g[lane]));
    const float bg = 1.0f - ag;
    const float as = 1.0f / (1.0f + expf(-tau_s[lane]));
    const float bs = 1.0f - as;

    const float W0d = 2.0f * w0;      // exact power-of-2 scalings
    const float BG2 = 2.0f * bg;
    const float BS2 = 2.0f * bs;

    const float2* xp = reinterpret_cast<const float2*>(x) + (size_t)b * TT;

    float v = 0.0f, V = 0.0f;
    int acc = 0;

    // Prime buffer 0
    float2 nxt = xp[lane];
    sbuf[wib][0][lane] = nxt;
    __syncwarp();
    int cur = 0;

    #pragma unroll 1
    for (int chunk = 0; chunk < 24; ++chunk) {
        nxt = xp[(chunk + 1) * 32 + lane];          // GMEM prefetch next chunk
        run32<false>(sbuf[wib][cur], v, V, acc, W0d, w1, ag, BG2, as, BS2);
        sbuf[wib][cur ^ 1][lane] = nxt;
        __syncwarp();
        cur ^= 1;
    }
    #pragma unroll 1
    for (int chunk = 24; chunk < 32; ++chunk) {
        if (chunk + 1 < 32) nxt = xp[(chunk + 1) * 32 + lane];
        run32<true>(sbuf[wib][cur], v, V, acc, W0d, w1, ag, BG2, as, BS2);
        if (chunk + 1 < 32) sbuf[wib][cur ^ 1][lane] = nxt;
        __syncwarp();
        cur ^= 1;
    }

    // out[b] = sum_h acc_h * Wout[h] + bout  (identical reduction tree)
    float val = __fmul_rn((float)acc, Wout[lane]);
    #pragma unroll
    for (int off = 16; off; off >>= 1)
        val += __shfl_xor_sync(0xffffffffu, val, off);
    if (lane == 0) out[b] = val + bout[0];
}

extern "C" void kernel_launch(void* const* d_in, const int* in_sizes, int n_in,
                              void* d_out, int out_size) {
    const float* x    = (const float*)d_in[0];
    const float* Wg   = (const float*)d_in[1];
    const float* taug = (const float*)d_in[2];
    const float* taus = (const float*)d_in[3];
    const float* Wout = (const float*)d_in[4];
    const float* bout = (const float*)d_in[5];
    float* out = (float*)d_out;

    // 1024 warps, uniform 2 warps/SMSP on 128 SMs: 128 blocks x 256 threads
    snn_kernel<<<128, 256>>>(x, Wg, taug, taus, Wout, bout, out);
}

// round 14
// speedup vs baseline: 1.1745x; 1.1745x over previous
#include <cuda_runtime.h>

// SNN recurrence: B=1024, T=1024, H=32, I=2. Lane = hidden unit.
// R14: ONE warp per SMSP carrying TWO batches' independent chains,
// interleaved scalar code (512 warps total, 128 blocks x 4 warps).
// Rationale: R8 (2 warps/SMSP) measured 73% issue efficiency — each warp's
// 15-instr step against its ~17-cyc dependence chain leaves stall holes that
// correlated across the two warps. Two independent chains INSIDE one warp
// give the scheduler fill material every cycle (demand/latency ~1.76).
// Arithmetic is R8's proven bit-exact predicated sequence (rel_err = 0.0).

#define TT 1024

__device__ __forceinline__ float uterm(float2 xv, float w0, float w1, float bg) {
    // bg*(x0*w0 + x1*w1), reference rounding order
    return __fmul_rn(bg, __fadd_rn(__fmul_rn(xv.x, w0), __fmul_rn(xv.y, w1)));
}

__device__ __forceinline__ void step_plain(float& v, float& V, float u,
                                           float ag, float as, float bs) {
    asm("{\n\t"
        ".reg .pred p, q;\n\t"
        "setp.gt.f32 p, %0, 0f3F800000;\n\t"   // s_{t-1} = v > 1
        "setp.gt.f32 q, %1, 0f3F800000;\n\t"   // S_{t-1} = V > 1
        "mul.rn.f32 %0, %0, %3;\n\t"           // v = ag*v
        "add.rn.f32 %0, %0, %2;\n\t"           // v += u
        "@p add.rn.f32 %0, %0, 0fBF800000;\n\t"// v -= 1   (reset)
        "setp.gt.f32 p, %0, 0f3F800000;\n\t"   // s_t = v > 1
        "mul.rn.f32 %1, %1, %4;\n\t"           // V = as*V
        "@p add.rn.f32 %1, %1, %5;\n\t"        // V += bs  (injection)
        "@q add.rn.f32 %1, %1, 0fBF800000;\n\t"// V -= 1   (reset)
        "}"
        : "+f"(v), "+f"(V)
        : "f"(u), "f"(ag), "f"(as), "f"(bs));
}

__device__ __forceinline__ void step_acc(float& v, float& V, int& acc, float u,
                                         float ag, float as, float bs) {
    asm("{\n\t"
        ".reg .pred p, q;\n\t"
        "setp.gt.f32 p, %0, 0f3F800000;\n\t"
        "setp.gt.f32 q, %1, 0f3F800000;\n\t"
        "mul.rn.f32 %0, %0, %4;\n\t"
        "add.rn.f32 %0, %0, %3;\n\t"
        "@p add.rn.f32 %0, %0, 0fBF800000;\n\t"
        "setp.gt.f32 p, %0, 0f3F800000;\n\t"
        "mul.rn.f32 %1, %1, %5;\n\t"
        "@p add.rn.f32 %1, %1, %6;\n\t"
        "@q add.rn.f32 %1, %1, 0fBF800000;\n\t"
        "setp.gt.f32 q, %1, 0f3F800000;\n\t"   // S_t
        "@q add.s32 %2, %2, 1;\n\t"            // spike count (alu pipe, exact)
        "}"
        : "+f"(v), "+f"(V), "+r"(acc)
        : "f"(u), "f"(ag), "f"(as), "f"(bs));
}

template <bool ACC>
__device__ __forceinline__ void run32(const float2* __restrict__ bufA,
                                      const float2* __restrict__ bufB,
                                      float& vA, float& VA, int& accA,
                                      float& vB, float& VB, int& accB,
                                      float w0, float w1, float ag, float bg,
                                      float as, float bs)
{
    float uA = uterm(bufA[0], w0, w1, bg);     // LDS exposed once per chunk
    float uB = uterm(bufB[0], w0, w1, bg);
    #pragma unroll
    for (int i = 0; i < 32; ++i) {
        float unA = 0.0f, unB = 0.0f;
        if (i < 31) {                          // off-chain prefetch, both chains
            unA = uterm(bufA[i + 1], w0, w1, bg);
            unB = uterm(bufB[i + 1], w0, w1, bg);
        }
        if (ACC) {
            step_acc(vA, VA, accA, uA, ag, as, bs);
            step_acc(vB, VB, accB, uB, ag, as, bs);
        } else {
            step_plain(vA, VA, uA, ag, as, bs);
            step_plain(vB, VB, uB, ag, as, bs);
        }
        uA = unA;
        uB = unB;
    }
}

__global__ __launch_bounds__(128, 1)
void snn_kernel(const float* __restrict__ x,
                const float* __restrict__ Wg,     // [32,2]
                const float* __restrict__ tau_g,  // [32]
                const float* __restrict__ tau_s,  // [32]
                const float* __restrict__ Wout,   // [32]
                const float* __restrict__ bout,   // [1]
                float* __restrict__ out)          // [1024]
{
    const int lane = threadIdx.x & 31;
    const int wib  = threadIdx.x >> 5;
    const int gw   = blockIdx.x * 4 + wib;   // global warp 0..511
    const int b0   = gw * 2;                 // two batches per warp

    __shared__ float2 sbufA[4][2][32];       // [warp][double buffer][step]
    __shared__ float2 sbufB[4][2][32];

    const float w0 = Wg[2 * lane];
    const float w1 = Wg[2 * lane + 1];
    const float ag = 1.0f / (1.0f + expf(-tau_g[lane]));
    const float bg = 1.0f - ag;
    const float as = 1.0f / (1.0f + expf(-tau_s[lane]));
    const float bs = 1.0f - as;

    const float2* xpA = reinterpret_cast<const float2*>(x) + (size_t)b0 * TT;
    const float2* xpB = xpA + TT;

    float vA = 0.0f, VA = 0.0f, vB = 0.0f, VB = 0.0f;
    int accA = 0, accB = 0;

    // Prime buffer 0 for both chains
    float2 nA = xpA[lane], nB = xpB[lane];
    sbufA[wib][0][lane] = nA;
    sbufB[wib][0][lane] = nB;
    __syncwarp();
    int cur = 0;

    #pragma unroll 1
    for (int chunk = 0; chunk < 24; ++chunk) {
        nA = xpA[(chunk + 1) * 32 + lane];   // GMEM prefetch next chunk
        nB = xpB[(chunk + 1) * 32 + lane];
        run32<false>(sbufA[wib][cur], sbufB[wib][cur],
                     vA, VA, accA, vB, VB, accB, w0, w1, ag, bg, as, bs);
        sbufA[wib][cur ^ 1][lane] = nA;
        sbufB[wib][cur ^ 1][lane] = nB;
        __syncwarp();
        cur ^= 1;
    }
    #pragma unroll 1
    for (int chunk = 24; chunk < 32; ++chunk) {
        if (chunk + 1 < 32) {
            nA = xpA[(chunk + 1) * 32 + lane];
            nB = xpB[(chunk + 1) * 32 + lane];
        }
        run32<true>(sbufA[wib][cur], sbufB[wib][cur],
                    vA, VA, accA, vB, VB, accB, w0, w1, ag, bg, as, bs);
        if (chunk + 1 < 32) {
            sbufA[wib][cur ^ 1][lane] = nA;
            sbufB[wib][cur ^ 1][lane] = nB;
        }
        __syncwarp();
        cur ^= 1;
    }

    // out[b] = sum_h acc_h * Wout[h] + bout  (identical reduction tree / batch)
    const float wl = Wout[lane];
    float valA = __fmul_rn((float)accA, wl);
    float valB = __fmul_rn((float)accB, wl);
    #pragma unroll
    for (int off = 16; off; off >>= 1) {
        valA += __shfl_xor_sync(0xffffffffu, valA, off);
        valB += __shfl_xor_sync(0xffffffffu, valB, off);
    }
    if (lane == 0) {
        const float bb = bout[0];
        out[b0]     = valA + bb;
        out[b0 + 1] = valB + bb;
    }
}

extern "C" void kernel_launch(void* const* d_in, const int* in_sizes, int n_in,
                              void* d_out, int out_size) {
    const float* x    = (const float*)d_in[0];
    const float* Wg   = (const float*)d_in[1];
    const float* taug = (const float*)d_in[2];
    const float* taus = (const float*)d_in[3];
    const float* Wout = (const float*)d_in[4];
    const float* bout = (const float*)d_in[5];
    float* out = (float*)d_out;

    // 512 warps, 2 chains each, 1 warp/SMSP: 128 blocks x 128 threads
    snn_kernel<<<128, 128>>>(x, Wg, taug, taus, Wout, bout, out);
}

// round 15
// speedup vs baseline: 1.1875x; 1.0111x over previous
#include <cuda_runtime.h>

// SNN recurrence: B=1024, T=1024, H=32, I=2. One warp/batch, lane = unit.
// 2 warps/SMSP (128 blocks x 256 threads). Bit-exact R8 op sequence,
// software-pipelined ACROSS iterations inside one asm block per 32-step chunk:
//   body k:  [acc S_{k-2}]  LDS x_{k+2}  u_{k+1}=uterm(x_{k+1})
//            V_{k-1} = as*V_{k-2} (+bs if s_{k-1}) (-1 if S_{k-2}); q=S_{k-1}
//            v_k = ag*v_{k-1} + u_k (-1 if s_{k-1});               p=s_k
// Every @p/@q guard consumes a pred set >= 1 body earlier (13-cyc pred-as-
// guard latency hidden); every LDS is consumed 1 body later (29-cyc hidden).
// Preds/x/u carried across chunks as float operands.

#define TT 1024

#define LD_B(OFF) "ld.shared.v2.f32 {xb0,xb1}, [%8+" OFF "];\n\t"
#define LD_A(OFF) "ld.shared.v2.f32 {xa0,xa1}, [%8+" OFF "];\n\t"

#define BODY_E(LDT, ACC) \
  LDT \
  "mul.rn.f32 t0, xa0, %10;\n\t" \
  "mul.rn.f32 t1, xa1, %11;\n\t" \
  "add.rn.f32 t0, t0, t1;\n\t" \
  "mul.rn.f32 ub, %12, t0;\n\t" \
  ACC \
  "mul.rn.f32 %1, %1, %14;\n\t" \
  "@p add.rn.f32 %1, %1, %15;\n\t" \
  "@q add.rn.f32 %1, %1, 0fBF800000;\n\t" \
  "setp.gt.f32 q, %1, 0f3F800000;\n\t" \
  "mul.rn.f32 %0, %0, %13;\n\t" \
  "add.rn.f32 %0, %0, ua;\n\t" \
  "@p add.rn.f32 %0, %0, 0fBF800000;\n\t" \
  "setp.gt.f32 p, %0, 0f3F800000;\n\t"

#define BODY_O(LDT, ACC) \
  LDT \
  "mul.rn.f32 t0, xb0, %10;\n\t" \
  "mul.rn.f32 t1, xb1, %11;\n\t" \
  "add.rn.f32 t0, t0, t1;\n\t" \
  "mul.rn.f32 ua, %12, t0;\n\t" \
  ACC \
  "mul.rn.f32 %1, %1, %14;\n\t" \
  "@p add.rn.f32 %1, %1, %15;\n\t" \
  "@q add.rn.f32 %1, %1, 0fBF800000;\n\t" \
  "setp.gt.f32 q, %1, 0f3F800000;\n\t" \
  "mul.rn.f32 %0, %0, %13;\n\t" \
  "add.rn.f32 %0, %0, ub;\n\t" \
  "@p add.rn.f32 %0, %0, 0fBF800000;\n\t" \
  "setp.gt.f32 p, %0, 0f3F800000;\n\t"

#define PAIR(OA, OB, ACC) BODY_E(LD_B(OA), ACC) BODY_O(LD_A(OB), ACC)

#define CHUNK_CORE(A01, A, TAIL) \
  "{\n\t" \
  ".reg .f32 xa0,xa1,xb0,xb1,t0,t1,ua,ub;\n\t" \
  ".reg .pred p,q;\n\t" \
  "mov.f32 ua, %2;\n\t" \
  "mov.f32 xa0, %6;\n\t" \
  "mov.f32 xa1, %7;\n\t" \
  "setp.gt.f32 p, %4, 0f3F000000;\n\t" \
  "setp.gt.f32 q, %5, 0f3F000000;\n\t" \
  BODY_E(LD_B("16"), A01) \
  BODY_O(LD_A("24"), A01) \
  PAIR("32","40",A)   PAIR("48","56",A)   PAIR("64","72",A)   PAIR("80","88",A) \
  PAIR("96","104",A)  PAIR("112","120",A) PAIR("128","136",A) PAIR("144","152",A) \
  PAIR("160","168",A) PAIR("176","184",A) PAIR("192","200",A) PAIR("208","216",A) \
  PAIR("224","232",A) \
  BODY_E(LD_B("240"), A) \
  BODY_O(LD_A("248"), A) \
  BODY_E("ld.shared.v2.f32 {xb0,xb1}, [%9];\n\t", A) \
  BODY_O("ld.shared.v2.f32 {xa0,xa1}, [%9+8];\n\t", A) \
  TAIL \
  "selp.f32 %4, 0f3F800000, 0f00000000, p;\n\t" \
  "selp.f32 %5, 0f3F800000, 0f00000000, q;\n\t" \
  "mov.f32 %2, ua;\n\t" \
  "mov.f32 %6, xa0;\n\t" \
  "mov.f32 %7, xa1;\n\t" \
  "}\n\t"

#define ACCQ "@q add.s32 %3, %3, 1;\n\t"

#define CHUNK_OPS \
  : "+f"(v), "+f"(V), "+f"(uc), "+r"(acc), "+f"(sF), "+f"(SF), "+f"(xc0), "+f"(xc1) \
  : "r"(cur), "r"(nxt), "f"(w0), "f"(w1), "f"(bg), "f"(ag), "f"(as), "f"(bs)

__global__ __launch_bounds__(256, 1)
void snn_kernel(const float* __restrict__ x,
                const float* __restrict__ Wg,     // [32,2]
                const float* __restrict__ tau_g,  // [32]
                const float* __restrict__ tau_s,  // [32]
                const float* __restrict__ Wout,   // [32]
                const float* __restrict__ bout,   // [1]
                float* __restrict__ out)          // [1024]
{
    const int lane = threadIdx.x & 31;
    const int wib  = threadIdx.x >> 5;
    const int b    = blockIdx.x * 8 + wib;

    __shared__ float2 sbuf[8][2][32];

    const float w0 = Wg[2 * lane];
    const float w1 = Wg[2 * lane + 1];
    const float ag = 1.0f / (1.0f + expf(-tau_g[lane]));
    const float bg = 1.0f - ag;
    const float as = 1.0f / (1.0f + expf(-tau_s[lane]));
    const float bs = 1.0f - as;

    const float2* xp = reinterpret_cast<const float2*>(x) + (size_t)b * TT;

    // Pipelined carries: uc = u_0, xc = x_1, spikes = 0
    float2 h0 = xp[0];
    float2 h1 = xp[1];
    float uc  = __fmul_rn(bg, __fadd_rn(__fmul_rn(h0.x, w0), __fmul_rn(h0.y, w1)));
    float xc0 = h1.x, xc1 = h1.y;
    float v = 0.0f, V = 0.0f, sF = 0.0f, SF = 0.0f;
    int acc = 0;

    // Prime both buffers: chunk 0 -> buf0, chunk 1 -> buf1
    sbuf[wib][0][lane] = xp[lane];
    sbuf[wib][1][lane] = xp[32 + lane];
    __syncwarp();

    const unsigned b0a = (unsigned)__cvta_generic_to_shared(&sbuf[wib][0][0]);
    const unsigned b1a = (unsigned)__cvta_generic_to_shared(&sbuf[wib][1][0]);

    #pragma unroll 1
    for (int c = 0; c < 32; ++c) {
        const unsigned cur = (c & 1) ? b1a : b0a;
        const unsigned nxt = (c & 1) ? b0a : b1a;
        float2 nd;
        if (c + 2 < 32) nd = xp[(c + 2) * 32 + lane];   // GMEM prefetch

        if (c < 24) {
            asm volatile(CHUNK_CORE("", "", "") CHUNK_OPS);
        } else if (c == 24) {
            asm volatile(CHUNK_CORE("", ACCQ, "") CHUNK_OPS);      // skip S_766,S_767
        } else if (c < 31) {
            asm volatile(CHUNK_CORE(ACCQ, ACCQ, "") CHUNK_OPS);
        } else {
            asm volatile(CHUNK_CORE(ACCQ, ACCQ, ACCQ) CHUNK_OPS);  // tail adds S_1022
        }

        if (c + 2 < 32) {
            sbuf[wib][c & 1][lane] = nd;
        }
        __syncwarp();
    }

    // Epilogue: finish soma step 1023 (body k computes V_{k-1}; last = V_1022).
    // V_1023 = as*V_1022 + bs*s_1023 - S_1022, exactly the R1 op sequence.
    {
        float m = __fmul_rn(bs, sF);                     // s_1023 in {0,1}
        float V1023 = __fsub_rn(__fadd_rn(__fmul_rn(as, V), m), SF);
        if (V1023 > 1.0f) acc += 1;                      // S_1023
    }

    // out[b] = sum_h acc_h * Wout[h] + bout  (identical reduction tree)
    float val = __fmul_rn((float)acc, Wout[lane]);
    #pragma unroll
    for (int off = 16; off; off >>= 1)
        val += __shfl_xor_sync(0xffffffffu, val, off);
    if (lane == 0) out[b] = val + bout[0];
}

extern "C" void kernel_launch(void* const* d_in, const int* in_sizes, int n_in,
                              void* d_out, int out_size) {
    const float* x    = (const float*)d_in[0];
    const float* Wg   = (const float*)d_in[1];
    const float* taug = (const float*)d_in[2];
    const float* taus = (const float*)d_in[3];
    const float* Wout = (const float*)d_in[4];
    const float* bout = (const float*)d_in[5];
    float* out = (float*)d_out;

    snn_kernel<<<128, 256>>>(x, Wg, taug, taus, Wout, bout, out);
}